// round 1
// baseline (speedup 1.0000x reference)
#include <cuda_runtime.h>

// Problem constants
#define BN    4096
#define NFEAT 1024
#define RR    64
#define KK    32
#define DD    16

// Tiling
#define BT      8     // b rows per block
#define RG      16    // regions per block
#define THREADS 256

#define XPITCH 1028   // smem pitch for raw x rows (bank-conflict-free gather)
#define GPITCH 136    // smem pitch per region for gathered tile [d][b] (+pad)

#define LOG_2PI_F 1.8378770664093453f

// Precomputed parameters (device globals: no allocation allowed)
__device__ float g_wa[RR * DD * KK];   // [r][d][k] = 1/scale
__device__ float g_wb[RR * DD * KK];   // [r][d][k] = -mean/scale
__device__ float g_c [RR * KK];        // [r][k]    = -sum_d log(scale) - 0.5*D*log(2pi)
__device__ int   g_idx[RR * DD];       // region indices as int32

// ---------------------------------------------------------------------------
// Prep kernel: single block of 1024 threads.
//  - detects int64 vs int32 regions at runtime (JAX x64 ambiguity)
//  - extracts indices, computes wa/wb (transposed layout) and C
// ---------------------------------------------------------------------------
__global__ void prep_kernel(const float* __restrict__ means,
                            const float* __restrict__ scales,
                            const void*  __restrict__ regions_raw) {
    __shared__ int s_is64;
    const int tid = threadIdx.x;

    if (tid == 0) {
        // If regions is int64 (values in [0,1024)), the high 32-bit words are 0.
        // Scan only the first 512 entries' worth (stays within 4KB either way).
        const int* w = (const int*)regions_raw;
        int orv = 0;
        for (int i = 1; i < 1024; i += 2) orv |= w[i];
        s_is64 = (orv == 0) ? 1 : 0;
    }
    __syncthreads();

    // Indices (tid < 1024 == RR*DD always)
    {
        const int* w = (const int*)regions_raw;
        g_idx[tid] = s_is64 ? w[2 * tid] : w[tid];
    }

    // Weights: 2048 (r,k) pairs handled by 1024 threads
    for (int t = tid; t < RR * KK; t += 1024) {
        const int r = t >> 5;
        const int k = t & 31;
        const float* sp = scales + (size_t)(r * KK + k) * DD;
        const float* mp = means  + (size_t)(r * KK + k) * DD;
        float su = 0.0f;
#pragma unroll
        for (int d = 0; d < DD; d++) {
            float s   = sp[d];
            float m   = mp[d];
            float inv = 1.0f / s;
            g_wa[(r * DD + d) * KK + k] = inv;
            g_wb[(r * DD + d) * KK + k] = -m * inv;
            su += logf(s);
        }
        g_c[t] = -su - 0.5f * (float)DD * LOG_2PI_F;
    }
}

// ---------------------------------------------------------------------------
// Main kernel: block = (BT=8 b-rows) x (RG=16 regions)
// Phase 1: coalesced load of x rows into smem
// Phase 2: gather xg[r][d][b] from smem
// Phase 3: register-tiled compute, 4b x 4k per thread, 2 FFMA per MAC
// ---------------------------------------------------------------------------
__global__ __launch_bounds__(THREADS, 4)
void main_kernel(const float* __restrict__ x, float* __restrict__ out) {
    __shared__ float sm_x [BT * XPITCH];   // 32,896 B
    __shared__ float sm_xg[RG * GPITCH];   //  8,704 B

    const int tid = threadIdx.x;
    const int b0  = blockIdx.x * BT;
    const int r0  = blockIdx.y * RG;

    // ---- Phase 1: load BT rows of x, fully coalesced float4 ----
    {
        const float4* xs = (const float4*)(x + (size_t)b0 * NFEAT);
#pragma unroll
        for (int i = tid; i < BT * (NFEAT / 4); i += THREADS) {
            const int row = i >> 8;     // NFEAT/4 == 256
            const int c   = i & 255;
            *(float4*)&sm_x[row * XPITCH + c * 4] = xs[row * 256 + c];
        }
    }
    __syncthreads();

    // ---- Phase 2: gather into sm_xg[rl][d*BT + b] ----
    // e = ((rl*BT + b) * DD + d): 16 lanes share (rl,b) and sweep d → random
    // banks on sm_x reads (pitch 1028 decorrelates b), 4-way STS at worst.
#pragma unroll
    for (int e = tid; e < RG * BT * DD; e += THREADS) {
        const int d  = e & (DD - 1);
        const int b  = (e >> 4) & (BT - 1);
        const int rl = e >> 7;
        const int col = g_idx[(r0 + rl) * DD + d];
        sm_xg[rl * GPITCH + d * BT + b] = sm_x[b * XPITCH + col];
    }
    __syncthreads();

    // ---- Phase 3: compute ----
    const int kg = tid & 7;          // k tile: kg*4 .. kg*4+3
    const int bg = (tid >> 3) & 1;   // b tile: bg*4 .. bg*4+3
    const int rl = tid >> 4;         // region within block: 0..15
    const int r  = r0 + rl;

    const float* wa = g_wa + r * DD * KK + kg * 4;
    const float* wb = g_wb + r * DD * KK + kg * 4;
    const float* xp = sm_xg + rl * GPITCH + bg * 4;

    float acc[16];
#pragma unroll
    for (int i = 0; i < 16; i++) acc[i] = 0.0f;

#pragma unroll
    for (int d = 0; d < DD; d++) {
        const float4 xv = *(const float4*)(xp + d * BT);
        const float4 a4 = *(const float4*)(wa + d * KK);
        const float4 b4 = *(const float4*)(wb + d * KK);
        const float xb[4] = {xv.x, xv.y, xv.z, xv.w};
        const float av[4] = {a4.x, a4.y, a4.z, a4.w};
        const float bv[4] = {b4.x, b4.y, b4.z, b4.w};
#pragma unroll
        for (int i = 0; i < 4; i++) {
#pragma unroll
            for (int j = 0; j < 4; j++) {
                const float z = fmaf(xb[i], av[j], bv[j]);
                acc[i * 4 + j] = fmaf(z, z, acc[i * 4 + j]);
            }
        }
    }

    // Epilogue: out[b][r][k] = -0.5*acc + C[r][k], float4 stores
    const float4 c4 = *(const float4*)(g_c + r * KK + kg * 4);
    const float cv[4] = {c4.x, c4.y, c4.z, c4.w};
#pragma unroll
    for (int i = 0; i < 4; i++) {
        const int b = b0 + bg * 4 + i;
        float4 o;
        o.x = fmaf(acc[i * 4 + 0], -0.5f, cv[0]);
        o.y = fmaf(acc[i * 4 + 1], -0.5f, cv[1]);
        o.z = fmaf(acc[i * 4 + 2], -0.5f, cv[2]);
        o.w = fmaf(acc[i * 4 + 3], -0.5f, cv[3]);
        *(float4*)&out[((size_t)b * RR + r) * KK + kg * 4] = o;
    }
}

// ---------------------------------------------------------------------------
extern "C" void kernel_launch(void* const* d_in, const int* in_sizes, int n_in,
                              void* d_out, int out_size) {
    const float* x       = (const float*)d_in[0];
    const void*  regions = d_in[1];                // int64 or int32, detected
    const float* means   = (const float*)d_in[2];
    const float* scales  = (const float*)d_in[3];
    float*       out     = (float*)d_out;

    prep_kernel<<<1, 1024>>>(means, scales, regions);

    dim3 grid(BN / BT, RR / RG);
    main_kernel<<<grid, THREADS>>>(x, out);
}

// round 2
// speedup vs baseline: 1.8441x; 1.8441x over previous
#include <cuda_runtime.h>

// Problem constants
#define BN    4096
#define NFEAT 1024
#define RR    64
#define KK    32
#define DD    16

// Tiling
#define BT      8     // b rows per block
#define RG      16    // regions per block
#define THREADS 256

#define XPITCH 1028   // smem pitch for raw x rows
#define GPITCH 132    // smem pitch per region for gathered tile [d][b] (+4 pad)

#define LOG_2PI_F 1.8378770664093453f

// Precomputed parameters (device globals: no allocation allowed)
__device__ float g_wa[RR * DD * KK];   // [r][d][k] = 1/scale
__device__ float g_wb[RR * DD * KK];   // [r][d][k] = -mean/scale
__device__ float g_c [RR * KK];        // [r][k]    = -sum_d log(scale) - 0.5*D*log(2pi)
__device__ int   g_idx[RR * DD];       // region indices as int32

// ---------------------------------------------------------------------------
// Prep kernel: 64 blocks (one per region) x 512 threads.
// Block r, thread t: k = t>>4, d = t&15 -> one (r,k,d) weight each.
// log_det reduced across the 16 d-lanes via shfl_xor.
// Block 0 additionally detects int64-vs-int32 regions and extracts indices.
// ---------------------------------------------------------------------------
__global__ void prep_kernel(const float* __restrict__ means,
                            const float* __restrict__ scales,
                            const void*  __restrict__ regions_raw) {
    const int r = blockIdx.x;
    const int t = threadIdx.x;       // 0..511
    const int k = t >> 4;
    const int d = t & 15;

    const float s   = scales[((size_t)r * KK + k) * DD + d];
    const float m   = means [((size_t)r * KK + k) * DD + d];
    const float inv = 1.0f / s;
    g_wa[(r * DD + d) * KK + k] = inv;
    g_wb[(r * DD + d) * KK + k] = -m * inv;

    float lg = logf(s);
#pragma unroll
    for (int o = 8; o >= 1; o >>= 1)
        lg += __shfl_xor_sync(0xffffffffu, lg, o);
    if (d == 0)
        g_c[r * KK + k] = -lg - 0.5f * (float)DD * LOG_2PI_F;

    if (r == 0) {
        // int64 detection: if regions is int64 (values < 1024), every odd
        // 32-bit word of the 2048-word buffer is zero. 512 threads cover all
        // odd words of the first 1024 32-bit words (enough either way).
        __shared__ int s_or;
        if (t == 0) s_or = 0;
        __syncthreads();
        const int* w = (const int*)regions_raw;
        int v = w[2 * t + 1];
#pragma unroll
        for (int o = 16; o >= 1; o >>= 1)
            v |= __shfl_xor_sync(0xffffffffu, v, o);
        if ((t & 31) == 0) atomicOr(&s_or, v);
        __syncthreads();
        const int is64 = (s_or == 0);
        g_idx[2 * t]     = is64 ? w[4 * t]     : w[2 * t];
        g_idx[2 * t + 1] = is64 ? w[4 * t + 2] : w[2 * t + 1];
    }
}

// ---------------------------------------------------------------------------
// Main kernel: block = (BT=8 b-rows) x (RG=16 regions), 256 threads.
// Thread (rl = tid>>4, kp = tid&15) computes an 8b x 2k output tile with
// ALL weights held in registers (loaded once), and x read via warp-broadcast
// LDS (all 16 lanes of a region read the same sm_xg address).
// ---------------------------------------------------------------------------
__global__ __launch_bounds__(THREADS, 2)
void main_kernel(const float* __restrict__ x, float* __restrict__ out) {
    __shared__ float sm_x [BT * XPITCH];   // 32,896 B
    __shared__ float sm_xg[RG * GPITCH];   //  8,448 B

    const int tid = threadIdx.x;
    const int b0  = blockIdx.x * BT;
    const int r0  = blockIdx.y * RG;

    const int rl = tid >> 4;         // region within block: 0..15
    const int kp = tid & 15;         // k-pair index: k0 = kp*2
    const int r  = r0 + rl;
    const int k0 = kp * 2;

    // ---- Preload this thread's weight slice into registers (64 regs) ----
    float2 wa2[DD], wb2[DD];
#pragma unroll
    for (int d = 0; d < DD; d++) {
        wa2[d] = *(const float2*)&g_wa[(r * DD + d) * KK + k0];
        wb2[d] = *(const float2*)&g_wb[(r * DD + d) * KK + k0];
    }

    // ---- Phase 1: load BT rows of x, fully coalesced float4 ----
    {
        const float4* xs = (const float4*)(x + (size_t)b0 * NFEAT);
#pragma unroll
        for (int i = tid; i < BT * (NFEAT / 4); i += THREADS) {
            const int row = i >> 8;     // NFEAT/4 == 256
            const int c   = i & 255;
            *(float4*)&sm_x[row * XPITCH + c * 4] = xs[row * 256 + c];
        }
    }
    __syncthreads();

    // ---- Phase 2: gather into sm_xg[rl][d*BT + b] (conflict-free STS) ----
#pragma unroll
    for (int j = 0; j < 8; j++) {
        const int e  = tid + j * THREADS;
        const int b  = e & (BT - 1);
        const int d  = (e >> 3) & (DD - 1);
        const int rg = e >> 7;
        const int col = g_idx[(r0 + rg) * DD + d];
        sm_xg[rg * GPITCH + d * BT + b] = sm_x[b * XPITCH + col];
    }
    __syncthreads();

    // ---- Phase 3: compute. 2 LDS.128 (broadcast) + 32 FFMA per d ----
    const float* xp = sm_xg + rl * GPITCH;

    float acc0[BT], acc1[BT];
#pragma unroll
    for (int i = 0; i < BT; i++) { acc0[i] = 0.0f; acc1[i] = 0.0f; }

#pragma unroll
    for (int d = 0; d < DD; d++) {
        const float4 xlo = *(const float4*)(xp + d * BT);
        const float4 xhi = *(const float4*)(xp + d * BT + 4);
        const float xb[BT] = {xlo.x, xlo.y, xlo.z, xlo.w,
                              xhi.x, xhi.y, xhi.z, xhi.w};
        const float a0 = wa2[d].x, a1 = wa2[d].y;
        const float c0 = wb2[d].x, c1 = wb2[d].y;
#pragma unroll
        for (int i = 0; i < BT; i++) {
            const float z0 = fmaf(xb[i], a0, c0);
            acc0[i] = fmaf(z0, z0, acc0[i]);
            const float z1 = fmaf(xb[i], a1, c1);
            acc1[i] = fmaf(z1, z1, acc1[i]);
        }
    }

    // ---- Epilogue: out[b][r][k0..k0+1], coalesced float2 stores ----
    const float2 c2 = *(const float2*)&g_c[r * KK + k0];
#pragma unroll
    for (int i = 0; i < BT; i++) {
        float2 o;
        o.x = fmaf(acc0[i], -0.5f, c2.x);
        o.y = fmaf(acc1[i], -0.5f, c2.y);
        *(float2*)&out[((size_t)(b0 + i) * RR + r) * KK + k0] = o;
    }
}

// ---------------------------------------------------------------------------
extern "C" void kernel_launch(void* const* d_in, const int* in_sizes, int n_in,
                              void* d_out, int out_size) {
    const float* x       = (const float*)d_in[0];
    const void*  regions = d_in[1];                // int64 or int32, detected
    const float* means   = (const float*)d_in[2];
    const float* scales  = (const float*)d_in[3];
    float*       out     = (float*)d_out;

    prep_kernel<<<RR, 512>>>(means, scales, regions);

    dim3 grid(BN / BT, RR / RG);
    main_kernel<<<grid, THREADS>>>(x, out);
}

// round 3
// speedup vs baseline: 2.0048x; 1.0871x over previous
#include <cuda_runtime.h>

// Problem constants
#define BN    4096
#define NFEAT 1024
#define RR    64
#define KK    32
#define DD    16

// Tiling
#define BT      8     // b rows per block
#define RG      16    // regions per block
#define THREADS 256

#define XPITCH 1028   // smem pitch for raw x rows
#define GPITCH 132    // smem pitch per region for gathered tile [d][b] (16B-aligned)

#define LOG_2PI_F 1.8378770664093453f

typedef unsigned long long u64;

// Packed fp32x2 helpers (sm_103a FFMA2 path — only reachable via PTX)
__device__ __forceinline__ u64 ffma2(u64 a, u64 b, u64 c) {
    u64 d;
    asm("fma.rn.f32x2 %0, %1, %2, %3;" : "=l"(d) : "l"(a), "l"(b), "l"(c));
    return d;
}
__device__ __forceinline__ u64 bcast2(float v) {
    u64 d;
    unsigned int r = __float_as_uint(v);
    asm("mov.b64 %0, {%1, %1};" : "=l"(d) : "r"(r));
    return d;
}
__device__ __forceinline__ void unpack2(u64 v, float& lo, float& hi) {
    unsigned int a, b;
    asm("mov.b64 {%0, %1}, %2;" : "=r"(a), "=r"(b) : "l"(v));
    lo = __uint_as_float(a);
    hi = __uint_as_float(b);
}

// Precomputed parameters (device globals: no allocation allowed)
__device__ float g_wa[RR * DD * KK];   // [r][d][k] = 1/scale
__device__ float g_wb[RR * DD * KK];   // [r][d][k] = -mean/scale
__device__ float g_c [RR * KK];        // [r][k]    = -sum_d log(scale) - 0.5*D*log(2pi)
__device__ int   g_idx[RR * DD];       // region indices as int32

// ---------------------------------------------------------------------------
// Prep kernel: 64 blocks (one per region) x 512 threads.
// ---------------------------------------------------------------------------
__global__ void prep_kernel(const float* __restrict__ means,
                            const float* __restrict__ scales,
                            const void*  __restrict__ regions_raw) {
    const int r = blockIdx.x;
    const int t = threadIdx.x;       // 0..511
    const int k = t >> 4;
    const int d = t & 15;

    const float s   = scales[((size_t)r * KK + k) * DD + d];
    const float m   = means [((size_t)r * KK + k) * DD + d];
    const float inv = 1.0f / s;
    g_wa[(r * DD + d) * KK + k] = inv;
    g_wb[(r * DD + d) * KK + k] = -m * inv;

    float lg = logf(s);
#pragma unroll
    for (int o = 8; o >= 1; o >>= 1)
        lg += __shfl_xor_sync(0xffffffffu, lg, o);
    if (d == 0)
        g_c[r * KK + k] = -lg - 0.5f * (float)DD * LOG_2PI_F;

    if (r == 0) {
        // int64 detection: if regions is int64 (values < 1024), every odd
        // 32-bit word is zero.
        __shared__ int s_or;
        if (t == 0) s_or = 0;
        __syncthreads();
        const int* w = (const int*)regions_raw;
        int v = w[2 * t + 1];
#pragma unroll
        for (int o = 16; o >= 1; o >>= 1)
            v |= __shfl_xor_sync(0xffffffffu, v, o);
        if ((t & 31) == 0) atomicOr(&s_or, v);
        __syncthreads();
        const int is64 = (s_or == 0);
        g_idx[2 * t]     = is64 ? w[4 * t]     : w[2 * t];
        g_idx[2 * t + 1] = is64 ? w[4 * t + 2] : w[2 * t + 1];
    }
}

// ---------------------------------------------------------------------------
// Main kernel: block = (BT=8 b-rows) x (RG=16 regions), 256 threads.
// Thread (rl, kp) computes an 8b x 2k tile using packed fp32x2 FMA:
// accumulators packed over b-pairs; x loaded as ready-packed ulonglong2 from
// the b-major gathered tile; weights broadcast-packed per d (4 movs).
// Weights held in registers 8 d at a time (2 halves) to keep regs <= 85
// for 3 blocks/SM.
// ---------------------------------------------------------------------------
__global__ __launch_bounds__(THREADS, 3)
void main_kernel(const float* __restrict__ x, float* __restrict__ out) {
    __shared__ float sm_x [BT * XPITCH];   // 32,896 B
    __shared__ float sm_xg[RG * GPITCH];   //  8,448 B

    const int tid = threadIdx.x;
    const int b0  = blockIdx.x * BT;
    const int r0  = blockIdx.y * RG;

    const int rl = tid >> 4;         // region within block: 0..15
    const int kp = tid & 15;         // k-pair index: k0 = kp*2
    const int r  = r0 + rl;
    const int k0 = kp * 2;

    // ---- Phase 1: load BT rows of x, fully coalesced float4 ----
    {
        const float4* xs = (const float4*)(x + (size_t)b0 * NFEAT);
#pragma unroll
        for (int i = tid; i < BT * (NFEAT / 4); i += THREADS) {
            const int row = i >> 8;     // NFEAT/4 == 256
            const int c   = i & 255;
            *(float4*)&sm_x[row * XPITCH + c * 4] = xs[row * 256 + c];
        }
    }
    __syncthreads();

    // ---- Phase 2: gather into sm_xg[rl][d*BT + b] ----
#pragma unroll
    for (int j = 0; j < 8; j++) {
        const int e  = tid + j * THREADS;
        const int b  = e & (BT - 1);
        const int d  = (e >> 3) & (DD - 1);
        const int rg = e >> 7;
        const int col = g_idx[(r0 + rg) * DD + d];
        sm_xg[rg * GPITCH + d * BT + b] = sm_x[b * XPITCH + col];
    }
    __syncthreads();

    // ---- Phase 3: packed compute ----
    const float* xp = sm_xg + rl * GPITCH;

    u64 acc0[4], acc1[4];
#pragma unroll
    for (int p = 0; p < 4; p++) { acc0[p] = 0ull; acc1[p] = 0ull; }

#pragma unroll 1
    for (int half = 0; half < 2; half++) {
        // Load this half's weight slice (8 d x 2 k, a and b): 32 regs
        float2 wa2[8], wb2[8];
        const int dbase = half * 8;
#pragma unroll
        for (int d = 0; d < 8; d++) {
            wa2[d] = *(const float2*)&g_wa[(r * DD + dbase + d) * KK + k0];
            wb2[d] = *(const float2*)&g_wb[(r * DD + dbase + d) * KK + k0];
        }

#pragma unroll
        for (int d = 0; d < 8; d++) {
            // x for 8 b's, already packed as 4 (b,b+1) fp32 pairs
            const ulonglong2 xA = *(const ulonglong2*)(xp + (dbase + d) * BT);
            const ulonglong2 xB = *(const ulonglong2*)(xp + (dbase + d) * BT + 4);
            const u64 xv[4] = {xA.x, xA.y, xB.x, xB.y};

            const u64 aa0 = bcast2(wa2[d].x);
            const u64 aa1 = bcast2(wa2[d].y);
            const u64 bb0 = bcast2(wb2[d].x);
            const u64 bb1 = bcast2(wb2[d].y);
#pragma unroll
            for (int p = 0; p < 4; p++) {
                const u64 z0 = ffma2(xv[p], aa0, bb0);
                acc0[p] = ffma2(z0, z0, acc0[p]);
                const u64 z1 = ffma2(xv[p], aa1, bb1);
                acc1[p] = ffma2(z1, z1, acc1[p]);
            }
        }
    }

    // ---- Epilogue: out[b][r][k0..k0+1] = -0.5*acc + C ----
    const float2 c2 = *(const float2*)&g_c[r * KK + k0];
    const u64 nh  = bcast2(-0.5f);
    const u64 cc0 = bcast2(c2.x);
    const u64 cc1 = bcast2(c2.y);
#pragma unroll
    for (int p = 0; p < 4; p++) {
        const u64 o0 = ffma2(acc0[p], nh, cc0);  // k0 for b=2p, 2p+1
        const u64 o1 = ffma2(acc1[p], nh, cc1);  // k1 for b=2p, 2p+1
        float o0lo, o0hi, o1lo, o1hi;
        unpack2(o0, o0lo, o0hi);
        unpack2(o1, o1lo, o1hi);
        float2 s0 = make_float2(o0lo, o1lo);
        float2 s1 = make_float2(o0hi, o1hi);
        *(float2*)&out[((size_t)(b0 + 2 * p)     * RR + r) * KK + k0] = s0;
        *(float2*)&out[((size_t)(b0 + 2 * p + 1) * RR + r) * KK + k0] = s1;
    }
}

// ---------------------------------------------------------------------------
extern "C" void kernel_launch(void* const* d_in, const int* in_sizes, int n_in,
                              void* d_out, int out_size) {
    const float* x       = (const float*)d_in[0];
    const void*  regions = d_in[1];                // int64 or int32, detected
    const float* means   = (const float*)d_in[2];
    const float* scales  = (const float*)d_in[3];
    float*       out     = (float*)d_out;

    prep_kernel<<<RR, 512>>>(means, scales, regions);

    dim3 grid(BN / BT, RR / RG);
    main_kernel<<<grid, THREADS>>>(x, out);
}